// round 9
// baseline (speedup 1.0000x reference)
#include <cuda_runtime.h>
#include <cstdint>

// RandomSaltPepper — bit-exact JAX threefry (partitionable path).
// R7 = R5 epilogue + R3 wide-mul rotate + relaxed register budget.
// Round = IMAD (add, fma pipe) + IMAD.WIDE (rotate halves, fma pipe) + 1 LOP3
// ((lo|hi)^x0, alu pipe): same issue count as SHF form, HALF the alu ops.
// R3 failed only because ptxas's 32-reg budget couldn't hold the pair-aligned
// wide destinations for 8 live chains; __launch_bounds__(256,1) fixes that.
// Rotation multipliers 2^r are runtime args so ptxas can't fold back to SHF.

struct TFParams {
    // keys: [0]=k0 [1]=k1 [2]=ks2 [3]=ks2+1 [4]=k0+2 [5]=k1+3 [6]=ks2+4 [7]=k0+5 (mask)
    //       [8..15] same layout (color)
    uint32_t k[16];
    // mult[i] = 1u << r, r in {13,15,26,6,17,29,16,24}
    uint32_t mult[8];
};

// add forced onto the fma pipe: r = a*one + b (one == 1 at runtime)
__device__ __forceinline__ uint32_t madd(uint32_t a, uint32_t one, uint32_t b) {
    uint32_t r;
    asm("mad.lo.u32 %0, %1, %2, %3;" : "=r"(r) : "r"(a), "r"(one), "r"(b));
    return r;
}

// round: x0 += x1; x1 = rotl(x1,r) ^ x0   via wide multiply
__device__ __forceinline__ void tf_round(uint32_t& x0, uint32_t& x1,
                                         uint32_t mult, uint32_t one) {
    x0 = madd(x1, one, x0);                                 // IMAD (fma)
    unsigned long long w = (unsigned long long)x1 * mult;   // IMAD.WIDE (fma)
    uint32_t lo = (uint32_t)w;                              //  = x1 << r
    uint32_t hi = (uint32_t)(w >> 32);                      //  = x1 >> (32-r)
    x1 = (lo | hi) ^ x0;                                    // single LOP3 (alu)
}

// threefry2x32, counter = (0, ctr), returns o0 ^ o1
__device__ __forceinline__ uint32_t tf_xor(const uint32_t* __restrict__ K,
                                           const uint32_t* __restrict__ M,
                                           uint32_t ctr, uint32_t one) {
    uint32_t x0 = K[0];
    uint32_t x1 = madd(ctr, one, K[1]);
    tf_round(x0,x1,M[0],one); tf_round(x0,x1,M[1],one); tf_round(x0,x1,M[2],one); tf_round(x0,x1,M[3],one);
    x0 = madd(K[1], one, x0);  x1 = madd(K[3], one, x1);   // += k1, += ks2+1
    tf_round(x0,x1,M[4],one); tf_round(x0,x1,M[5],one); tf_round(x0,x1,M[6],one); tf_round(x0,x1,M[7],one);
    x0 = madd(K[2], one, x0);  x1 = madd(K[4], one, x1);   // += ks2, += k0+2
    tf_round(x0,x1,M[0],one); tf_round(x0,x1,M[1],one); tf_round(x0,x1,M[2],one); tf_round(x0,x1,M[3],one);
    x0 = madd(K[0], one, x0);  x1 = madd(K[5], one, x1);   // += k0,  += k1+3
    tf_round(x0,x1,M[4],one); tf_round(x0,x1,M[5],one); tf_round(x0,x1,M[6],one); tf_round(x0,x1,M[7],one);
    x0 = madd(K[1], one, x0);  x1 = madd(K[6], one, x1);   // += k1,  += ks2+4
    tf_round(x0,x1,M[0],one); tf_round(x0,x1,M[1],one); tf_round(x0,x1,M[2],one); tf_round(x0,x1,M[3],one);
    x0 = madd(K[2], one, x0);  x1 = madd(K[7], one, x1);   // += ks2, += k0+5
    return x0 ^ x1;
}

// ---------------- host threefry2x32 (key derivation) ----------------
static void tf_round_h(uint32_t& x0, uint32_t& x1, int r) {
    x0 += x1;
    x1 = (x1 << r) | (x1 >> (32 - r));
    x1 ^= x0;
}
static void tf_host(uint32_t k0, uint32_t k1, uint32_t x0in, uint32_t x1in,
                    uint32_t& o0, uint32_t& o1) {
    uint32_t ks2 = k0 ^ k1 ^ 0x1BD11BDAu;
    uint32_t x0 = x0in + k0;
    uint32_t x1 = x1in + k1;
    tf_round_h(x0,x1,13); tf_round_h(x0,x1,15); tf_round_h(x0,x1,26); tf_round_h(x0,x1, 6);
    x0 += k1;  x1 += ks2 + 1u;
    tf_round_h(x0,x1,17); tf_round_h(x0,x1,29); tf_round_h(x0,x1,16); tf_round_h(x0,x1,24);
    x0 += ks2; x1 += k0 + 2u;
    tf_round_h(x0,x1,13); tf_round_h(x0,x1,15); tf_round_h(x0,x1,26); tf_round_h(x0,x1, 6);
    x0 += k0;  x1 += k1 + 3u;
    tf_round_h(x0,x1,17); tf_round_h(x0,x1,29); tf_round_h(x0,x1,16); tf_round_h(x0,x1,24);
    x0 += k1;  x1 += ks2 + 4u;
    tf_round_h(x0,x1,13); tf_round_h(x0,x1,15); tf_round_h(x0,x1,26); tf_round_h(x0,x1, 6);
    x0 += ks2; x1 += k0 + 5u;
    o0 = x0; o1 = x1;
}

// ---------------- kernel ----------------
// B=64, C=3, H=W=512. HW = 2^18, positions P = 2^24. 4 consecutive positions/thread.
__global__ __launch_bounds__(256, 1)
void RandomSaltPepper_9380208574641_kernel(
    const float4* __restrict__ in, float4* __restrict__ out,
    TFParams prm, uint32_t one, uint32_t two, uint32_t fone)
{
    const uint32_t* __restrict__ MK = prm.k;       // mask key block
    const uint32_t* __restrict__ CK = prm.k + 8;   // color key block
    const uint32_t* __restrict__ M  = prm.mult;    // rotation multipliers (runtime)

    uint32_t t  = blockIdx.x * blockDim.x + threadIdx.x;   // 0 .. 2^22-1
    uint32_t p0 = t << 2;                                  // base (b,h,w) index
    uint32_t b  = p0 >> 18;                                // batch
    uint32_t q4 = (p0 & 0x3FFFFu) >> 2;                    // float4 index within HW

    // hoist loads — latency hides under ~600 ALU/FMA instructions below
    uint32_t i0 = ((b * 3u + 0u) << 16) + q4;
    uint32_t i1 = i0 + (1u << 16);
    uint32_t i2 = i0 + (2u << 16);
    float4 v0 = in[i0];
    float4 v1 = in[i1];
    float4 v2 = in[i2];

    // z[i] = 1.0f if position keeps the image (mask false), else 0.0f
    // s[i] = 1.0f if masked AND salt, else 0.0f            out = v*z + s
    float z[4], s[4];
#pragma unroll
    for (int i = 0; i < 4; i++) {
        uint32_t bu = tf_xor(MK, M, p0 + i, one);
        uint32_t bc = tf_xor(CK, M, p0 + i, one);
        uint32_t tb = __umulhi(bu, two);               // bit31(bu): 1 = keep image (fma)
        uint32_t sb = (~tb) & (~bc) & 1u;              // masked & salt (one LOP3)
        z[i] = __uint_as_float(tb * fone);             // IMAD (fma): 0x3F800000 or 0
        s[i] = __uint_as_float(sb * fone);             // IMAD (fma)
    }

    float4 o0, o1, o2;
    o0.x = fmaf(v0.x, z[0], s[0]);  o0.y = fmaf(v0.y, z[1], s[1]);
    o0.z = fmaf(v0.z, z[2], s[2]);  o0.w = fmaf(v0.w, z[3], s[3]);
    o1.x = fmaf(v1.x, z[0], s[0]);  o1.y = fmaf(v1.y, z[1], s[1]);
    o1.z = fmaf(v1.z, z[2], s[2]);  o1.w = fmaf(v1.w, z[3], s[3]);
    o2.x = fmaf(v2.x, z[0], s[0]);  o2.y = fmaf(v2.y, z[1], s[1]);
    o2.z = fmaf(v2.z, z[2], s[2]);  o2.w = fmaf(v2.w, z[3], s[3]);
    out[i0] = o0;
    out[i1] = o1;
    out[i2] = o2;
}

extern "C" void kernel_launch(void* const* d_in, const int* in_sizes, int n_in,
                              void* d_out, int out_size)
{
    const float4* in  = (const float4*)d_in[0];
    float4*       out = (float4*)d_out;

    // ---- derive JAX keys on host ----
    uint32_t k1a, k1b, k2a, k2b;
    tf_host(0u, 42u, 0u, 0u, k1a, k1b);          // k1 = split(root)[0]
    tf_host(0u, 42u, 0u, 1u, k2a, k2b);          // k2 = split(root)[1]
    uint32_t kb0, kb1;
    tf_host(k2a, k2b, 0u, 1u, kb0, kb1);         // randint internal split, child 1

    TFParams prm;
    {
        uint32_t k0 = k1a, k1 = k1b, ks2 = k0 ^ k1 ^ 0x1BD11BDAu;
        uint32_t* K = prm.k;
        K[0]=k0; K[1]=k1; K[2]=ks2; K[3]=ks2+1u; K[4]=k0+2u; K[5]=k1+3u; K[6]=ks2+4u; K[7]=k0+5u;
    }
    {
        uint32_t k0 = kb0, k1 = kb1, ks2 = k0 ^ k1 ^ 0x1BD11BDAu;
        uint32_t* K = prm.k + 8;
        K[0]=k0; K[1]=k1; K[2]=ks2; K[3]=ks2+1u; K[4]=k0+2u; K[5]=k1+3u; K[6]=ks2+4u; K[7]=k0+5u;
    }
    static const int rots[8] = {13, 15, 26, 6, 17, 29, 16, 24};
    for (int i = 0; i < 8; i++) prm.mult[i] = 1u << rots[i];

    const int threads = 256;
    const int blocks  = (1 << 22) / threads;     // 16384
    RandomSaltPepper_9380208574641_kernel<<<blocks, threads>>>(
        in, out, prm, 1u, 2u, 0x3F800000u);
}

// round 10
// speedup vs baseline: 1.5004x; 1.5004x over previous
#include <cuda_runtime.h>
#include <cstdint>

// RandomSaltPepper — bit-exact JAX threefry (partitionable path).
// R8 = R5 RNG core (IMAD adds on fma pipe + SHF/LOP3 rotate on alu pipe, FFMA
// blend epilogue) restructured as a PERSISTENT grid-stride kernel with a
// one-iteration software pipeline: next tile's float4 loads are issued before
// the current tile's RNG, giving each load a full iteration (~650 cyc) of ALU
// cover instead of ~570 instr, and eliminating 110 block-launch waves.

struct TFParams {
    // keys: [0]=k0 [1]=k1 [2]=ks2 [3]=ks2+1 [4]=k0+2 [5]=k1+3 [6]=ks2+4 [7]=k0+5 (mask)
    //       [8..15] same layout (color)
    uint32_t k[16];
};

// add forced onto the fma pipe: r = a*one + b (one == 1 at runtime)
__device__ __forceinline__ uint32_t madd(uint32_t a, uint32_t one, uint32_t b) {
    uint32_t r;
    asm("mad.lo.u32 %0, %1, %2, %3;" : "=r"(r) : "r"(a), "r"(one), "r"(b));
    return r;
}

__device__ __forceinline__ void tf_round(uint32_t& x0, uint32_t& x1, int r, uint32_t one) {
    x0 = madd(x1, one, x0);                       // IMAD  (fma pipe)
    x1 = __funnelshift_l(x1, x1, r) ^ x0;         // SHF + LOP3 (alu pipe)
}

// threefry2x32, counter = (0, ctr), returns o0 ^ o1
__device__ __forceinline__ uint32_t tf_xor(const uint32_t* __restrict__ K,
                                           uint32_t ctr, uint32_t one) {
    uint32_t x0 = K[0];
    uint32_t x1 = madd(ctr, one, K[1]);
    tf_round(x0,x1,13,one); tf_round(x0,x1,15,one); tf_round(x0,x1,26,one); tf_round(x0,x1, 6,one);
    x0 = madd(K[1], one, x0);  x1 = madd(K[3], one, x1);   // += k1, += ks2+1
    tf_round(x0,x1,17,one); tf_round(x0,x1,29,one); tf_round(x0,x1,16,one); tf_round(x0,x1,24,one);
    x0 = madd(K[2], one, x0);  x1 = madd(K[4], one, x1);   // += ks2, += k0+2
    tf_round(x0,x1,13,one); tf_round(x0,x1,15,one); tf_round(x0,x1,26,one); tf_round(x0,x1, 6,one);
    x0 = madd(K[0], one, x0);  x1 = madd(K[5], one, x1);   // += k0,  += k1+3
    tf_round(x0,x1,17,one); tf_round(x0,x1,29,one); tf_round(x0,x1,16,one); tf_round(x0,x1,24,one);
    x0 = madd(K[1], one, x0);  x1 = madd(K[6], one, x1);   // += k1,  += ks2+4
    tf_round(x0,x1,13,one); tf_round(x0,x1,15,one); tf_round(x0,x1,26,one); tf_round(x0,x1, 6,one);
    x0 = madd(K[2], one, x0);  x1 = madd(K[7], one, x1);   // += ks2, += k0+5
    return x0 ^ x1;
}

// ---------------- host threefry2x32 (key derivation) ----------------
static void tf_round_h(uint32_t& x0, uint32_t& x1, int r) {
    x0 += x1;
    x1 = (x1 << r) | (x1 >> (32 - r));
    x1 ^= x0;
}
static void tf_host(uint32_t k0, uint32_t k1, uint32_t x0in, uint32_t x1in,
                    uint32_t& o0, uint32_t& o1) {
    uint32_t ks2 = k0 ^ k1 ^ 0x1BD11BDAu;
    uint32_t x0 = x0in + k0;
    uint32_t x1 = x1in + k1;
    tf_round_h(x0,x1,13); tf_round_h(x0,x1,15); tf_round_h(x0,x1,26); tf_round_h(x0,x1, 6);
    x0 += k1;  x1 += ks2 + 1u;
    tf_round_h(x0,x1,17); tf_round_h(x0,x1,29); tf_round_h(x0,x1,16); tf_round_h(x0,x1,24);
    x0 += ks2; x1 += k0 + 2u;
    tf_round_h(x0,x1,13); tf_round_h(x0,x1,15); tf_round_h(x0,x1,26); tf_round_h(x0,x1, 6);
    x0 += k0;  x1 += k1 + 3u;
    tf_round_h(x0,x1,17); tf_round_h(x0,x1,29); tf_round_h(x0,x1,16); tf_round_h(x0,x1,24);
    x0 += k1;  x1 += ks2 + 4u;
    tf_round_h(x0,x1,13); tf_round_h(x0,x1,15); tf_round_h(x0,x1,26); tf_round_h(x0,x1, 6);
    x0 += ks2; x1 += k0 + 5u;
    o0 = x0; o1 = x1;
}

// index helper: thread-task tt -> the three float4 indices for its 4 positions
__device__ __forceinline__ void calc_idx(uint32_t tt, uint32_t& i0, uint32_t& i1, uint32_t& i2) {
    uint32_t p0 = tt << 2;
    uint32_t b  = p0 >> 18;                       // batch
    uint32_t q4 = (p0 & 0x3FFFFu) >> 2;           // float4 index within HW (2^16 per plane)
    i0 = ((b * 3u) << 16) + q4;
    i1 = i0 + (1u << 16);
    i2 = i0 + (2u << 16);
}

// ---------------- kernel ----------------
// B=64, C=3, H=W=512. HW = 2^18, positions P = 2^24, thread-tasks T = 2^22
// (4 consecutive positions per task). Persistent: 592 blocks grid-stride.
__global__ __launch_bounds__(256, 1)
void RandomSaltPepper_9380208574641_kernel(
    const float4* __restrict__ in, float4* __restrict__ out,
    TFParams prm, uint32_t one, uint32_t two, uint32_t fone, uint32_t T)
{
    const uint32_t* __restrict__ MK = prm.k;       // mask key block
    const uint32_t* __restrict__ CK = prm.k + 8;   // color key block

    const uint32_t stride = gridDim.x * blockDim.x;
    uint32_t t = blockIdx.x * blockDim.x + threadIdx.x;
    if (t >= T) return;

    // prologue: load tile for first task
    uint32_t i0, i1, i2;
    calc_idx(t, i0, i1, i2);
    float4 v0 = in[i0];
    float4 v1 = in[i1];
    float4 v2 = in[i2];

    for (;;) {
        // ---- software pipeline: issue NEXT tile's loads first ----
        uint32_t tn = t + stride;
        bool has_next = tn < T;
        uint32_t j0 = 0, j1 = 0, j2 = 0;
        float4 n0, n1, n2;
        if (has_next) {
            calc_idx(tn, j0, j1, j2);
            n0 = in[j0];
            n1 = in[j1];
            n2 = in[j2];
        }

        // ---- RNG for CURRENT task (covers this iter's stores + next loads) ----
        uint32_t p0 = t << 2;
        float z[4], s[4];
#pragma unroll
        for (int i = 0; i < 4; i++) {
            uint32_t bu = tf_xor(MK, p0 + i, one);
            uint32_t bc = tf_xor(CK, p0 + i, one);
            uint32_t tb = __umulhi(bu, two);           // bit31(bu): 1 = keep image (fma)
            uint32_t sb = (~tb) & (~bc) & 1u;          // masked & salt (one LOP3)
            z[i] = __uint_as_float(tb * fone);         // IMAD (fma): 0x3F800000 or 0
            s[i] = __uint_as_float(sb * fone);         // IMAD (fma)
        }

        float4 o0, o1, o2;
        o0.x = fmaf(v0.x, z[0], s[0]);  o0.y = fmaf(v0.y, z[1], s[1]);
        o0.z = fmaf(v0.z, z[2], s[2]);  o0.w = fmaf(v0.w, z[3], s[3]);
        o1.x = fmaf(v1.x, z[0], s[0]);  o1.y = fmaf(v1.y, z[1], s[1]);
        o1.z = fmaf(v1.z, z[2], s[2]);  o1.w = fmaf(v1.w, z[3], s[3]);
        o2.x = fmaf(v2.x, z[0], s[0]);  o2.y = fmaf(v2.y, z[1], s[1]);
        o2.z = fmaf(v2.z, z[2], s[2]);  o2.w = fmaf(v2.w, z[3], s[3]);
        out[i0] = o0;
        out[i1] = o1;
        out[i2] = o2;

        if (!has_next) break;
        t = tn;
        i0 = j0; i1 = j1; i2 = j2;
        v0 = n0; v1 = n1; v2 = n2;
    }
}

extern "C" void kernel_launch(void* const* d_in, const int* in_sizes, int n_in,
                              void* d_out, int out_size)
{
    const float4* in  = (const float4*)d_in[0];
    float4*       out = (float4*)d_out;

    // ---- derive JAX keys on host ----
    uint32_t k1a, k1b, k2a, k2b;
    tf_host(0u, 42u, 0u, 0u, k1a, k1b);          // k1 = split(root)[0]
    tf_host(0u, 42u, 0u, 1u, k2a, k2b);          // k2 = split(root)[1]
    uint32_t kb0, kb1;
    tf_host(k2a, k2b, 0u, 1u, kb0, kb1);         // randint internal split, child 1

    TFParams prm;
    {
        uint32_t k0 = k1a, k1 = k1b, ks2 = k0 ^ k1 ^ 0x1BD11BDAu;
        uint32_t* K = prm.k;
        K[0]=k0; K[1]=k1; K[2]=ks2; K[3]=ks2+1u; K[4]=k0+2u; K[5]=k1+3u; K[6]=ks2+4u; K[7]=k0+5u;
    }
    {
        uint32_t k0 = kb0, k1 = kb1, ks2 = k0 ^ k1 ^ 0x1BD11BDAu;
        uint32_t* K = prm.k + 8;
        K[0]=k0; K[1]=k1; K[2]=ks2; K[3]=ks2+1u; K[4]=k0+2u; K[5]=k1+3u; K[6]=ks2+4u; K[7]=k0+5u;
    }

    // persistent: 4 blocks per SM on 148 SMs
    const int threads = 256;
    const int blocks  = 148 * 4;                 // 592
    RandomSaltPepper_9380208574641_kernel<<<blocks, threads>>>(
        in, out, prm, 1u, 2u, 0x3F800000u, 1u << 22);
}

// round 11
// speedup vs baseline: 1.5341x; 1.0225x over previous
#include <cuda_runtime.h>
#include <cstdint>

// RandomSaltPepper — bit-exact JAX threefry (partitionable path).
// R9 = R5 op mix (IMAD adds on fma pipe via runtime-one mad, SHF+LOP3 rotate,
// FFMA blend epilogue) with the 8 threefry chains (4 mask + 4 color) advanced
// ROUND-MAJOR IN LOCKSTEP: round8() applies one round to all 8 state pairs
// before moving on. This hands ptxas a DAG with guaranteed 8-wide ILP at every
// instruction depth, eliminating the intra-chain RAW bubbles that capped R5 at
// issue=86.6%. Op counts are identical to R5; only the schedule shape changes.

struct TFParams {
    // keys: [0]=k0 [1]=k1 [2]=ks2 [3]=ks2+1 [4]=k0+2 [5]=k1+3 [6]=ks2+4 [7]=k0+5 (mask)
    //       [8..15] same layout (color)
    uint32_t k[16];
};

// add forced onto the fma pipe: r = a*one + b (one == 1 at runtime)
__device__ __forceinline__ uint32_t madd(uint32_t a, uint32_t one, uint32_t b) {
    uint32_t r;
    asm("mad.lo.u32 %0, %1, %2, %3;" : "=r"(r) : "r"(a), "r"(one), "r"(b));
    return r;
}

// one threefry round applied to all 8 chains (4 mask a*, 4 color c*)
__device__ __forceinline__ void round8(uint32_t* a0, uint32_t* a1,
                                       uint32_t* c0, uint32_t* c1,
                                       int r, uint32_t one) {
#pragma unroll
    for (int i = 0; i < 4; i++) {
        a0[i] = madd(a1[i], one, a0[i]);                    // IMAD (fma)
        a1[i] = __funnelshift_l(a1[i], a1[i], r) ^ a0[i];   // SHF + LOP3 (alu)
    }
#pragma unroll
    for (int i = 0; i < 4; i++) {
        c0[i] = madd(c1[i], one, c0[i]);
        c1[i] = __funnelshift_l(c1[i], c1[i], r) ^ c0[i];
    }
}

// key injection applied to all 8 chains
__device__ __forceinline__ void inject8(uint32_t* a0, uint32_t* a1,
                                        uint32_t* c0, uint32_t* c1,
                                        uint32_t ka0, uint32_t ka1,
                                        uint32_t kc0, uint32_t kc1, uint32_t one) {
#pragma unroll
    for (int i = 0; i < 4; i++) {
        a0[i] = madd(ka0, one, a0[i]);
        a1[i] = madd(ka1, one, a1[i]);
        c0[i] = madd(kc0, one, c0[i]);
        c1[i] = madd(kc1, one, c1[i]);
    }
}

// ---------------- host threefry2x32 (key derivation) ----------------
static void tf_round_h(uint32_t& x0, uint32_t& x1, int r) {
    x0 += x1;
    x1 = (x1 << r) | (x1 >> (32 - r));
    x1 ^= x0;
}
static void tf_host(uint32_t k0, uint32_t k1, uint32_t x0in, uint32_t x1in,
                    uint32_t& o0, uint32_t& o1) {
    uint32_t ks2 = k0 ^ k1 ^ 0x1BD11BDAu;
    uint32_t x0 = x0in + k0;
    uint32_t x1 = x1in + k1;
    tf_round_h(x0,x1,13); tf_round_h(x0,x1,15); tf_round_h(x0,x1,26); tf_round_h(x0,x1, 6);
    x0 += k1;  x1 += ks2 + 1u;
    tf_round_h(x0,x1,17); tf_round_h(x0,x1,29); tf_round_h(x0,x1,16); tf_round_h(x0,x1,24);
    x0 += ks2; x1 += k0 + 2u;
    tf_round_h(x0,x1,13); tf_round_h(x0,x1,15); tf_round_h(x0,x1,26); tf_round_h(x0,x1, 6);
    x0 += k0;  x1 += k1 + 3u;
    tf_round_h(x0,x1,17); tf_round_h(x0,x1,29); tf_round_h(x0,x1,16); tf_round_h(x0,x1,24);
    x0 += k1;  x1 += ks2 + 4u;
    tf_round_h(x0,x1,13); tf_round_h(x0,x1,15); tf_round_h(x0,x1,26); tf_round_h(x0,x1, 6);
    x0 += ks2; x1 += k0 + 5u;
    o0 = x0; o1 = x1;
}

// ---------------- kernel ----------------
// B=64, C=3, H=W=512. HW = 2^18, positions P = 2^24. 4 consecutive positions/thread.
__global__ __launch_bounds__(256, 1)
void RandomSaltPepper_9380208574641_kernel(
    const float4* __restrict__ in, float4* __restrict__ out,
    TFParams prm, uint32_t one, uint32_t two, uint32_t fone)
{
    uint32_t t  = blockIdx.x * blockDim.x + threadIdx.x;   // 0 .. 2^22-1
    uint32_t p0 = t << 2;                                  // base (b,h,w) index
    uint32_t b  = p0 >> 18;                                // batch
    uint32_t q4 = (p0 & 0x3FFFFu) >> 2;                    // float4 index within HW

    uint32_t i0 = ((b * 3u) << 16) + q4;
    uint32_t i1 = i0 + (1u << 16);
    uint32_t i2 = i0 + (2u << 16);
    float4 v0 = in[i0];
    float4 v1 = in[i1];
    float4 v2 = in[i2];

    // ---- 8 threefry chains in lockstep: a* = mask key, c* = color key ----
    uint32_t a0[4], a1[4], c0[4], c1[4];
#pragma unroll
    for (int i = 0; i < 4; i++) {
        a0[i] = prm.k[0];
        a1[i] = madd(p0 + i, one, prm.k[1]);
        c0[i] = prm.k[8];
        c1[i] = madd(p0 + i, one, prm.k[9]);
    }
    round8(a0,a1,c0,c1,13,one); round8(a0,a1,c0,c1,15,one);
    round8(a0,a1,c0,c1,26,one); round8(a0,a1,c0,c1, 6,one);
    inject8(a0,a1,c0,c1, prm.k[1], prm.k[3], prm.k[9],  prm.k[11], one); // +k1, +ks2+1
    round8(a0,a1,c0,c1,17,one); round8(a0,a1,c0,c1,29,one);
    round8(a0,a1,c0,c1,16,one); round8(a0,a1,c0,c1,24,one);
    inject8(a0,a1,c0,c1, prm.k[2], prm.k[4], prm.k[10], prm.k[12], one); // +ks2, +k0+2
    round8(a0,a1,c0,c1,13,one); round8(a0,a1,c0,c1,15,one);
    round8(a0,a1,c0,c1,26,one); round8(a0,a1,c0,c1, 6,one);
    inject8(a0,a1,c0,c1, prm.k[0], prm.k[5], prm.k[8],  prm.k[13], one); // +k0,  +k1+3
    round8(a0,a1,c0,c1,17,one); round8(a0,a1,c0,c1,29,one);
    round8(a0,a1,c0,c1,16,one); round8(a0,a1,c0,c1,24,one);
    inject8(a0,a1,c0,c1, prm.k[1], prm.k[6], prm.k[9],  prm.k[14], one); // +k1,  +ks2+4
    round8(a0,a1,c0,c1,13,one); round8(a0,a1,c0,c1,15,one);
    round8(a0,a1,c0,c1,26,one); round8(a0,a1,c0,c1, 6,one);
    inject8(a0,a1,c0,c1, prm.k[2], prm.k[7], prm.k[10], prm.k[15], one); // +ks2, +k0+5

    // z[i] = 1.0f if keep image, s[i] = 1.0f if masked & salt;  out = v*z + s
    float z[4], s[4];
#pragma unroll
    for (int i = 0; i < 4; i++) {
        uint32_t bu = a0[i] ^ a1[i];
        uint32_t bc = c0[i] ^ c1[i];
        uint32_t tb = __umulhi(bu, two);               // bit31(bu): 1 = keep image (fma)
        uint32_t sb = (~tb) & (~bc) & 1u;              // masked & salt (one LOP3)
        z[i] = __uint_as_float(tb * fone);             // IMAD (fma): 0x3F800000 or 0
        s[i] = __uint_as_float(sb * fone);             // IMAD (fma)
    }

    float4 o0, o1, o2;
    o0.x = fmaf(v0.x, z[0], s[0]);  o0.y = fmaf(v0.y, z[1], s[1]);
    o0.z = fmaf(v0.z, z[2], s[2]);  o0.w = fmaf(v0.w, z[3], s[3]);
    o1.x = fmaf(v1.x, z[0], s[0]);  o1.y = fmaf(v1.y, z[1], s[1]);
    o1.z = fmaf(v1.z, z[2], s[2]);  o1.w = fmaf(v1.w, z[3], s[3]);
    o2.x = fmaf(v2.x, z[0], s[0]);  o2.y = fmaf(v2.y, z[1], s[1]);
    o2.z = fmaf(v2.z, z[2], s[2]);  o2.w = fmaf(v2.w, z[3], s[3]);
    out[i0] = o0;
    out[i1] = o1;
    out[i2] = o2;
}

extern "C" void kernel_launch(void* const* d_in, const int* in_sizes, int n_in,
                              void* d_out, int out_size)
{
    const float4* in  = (const float4*)d_in[0];
    float4*       out = (float4*)d_out;

    // ---- derive JAX keys on host ----
    uint32_t k1a, k1b, k2a, k2b;
    tf_host(0u, 42u, 0u, 0u, k1a, k1b);          // k1 = split(root)[0]
    tf_host(0u, 42u, 0u, 1u, k2a, k2b);          // k2 = split(root)[1]
    uint32_t kb0, kb1;
    tf_host(k2a, k2b, 0u, 1u, kb0, kb1);         // randint internal split, child 1

    TFParams prm;
    {
        uint32_t k0 = k1a, k1 = k1b, ks2 = k0 ^ k1 ^ 0x1BD11BDAu;
        uint32_t* K = prm.k;
        K[0]=k0; K[1]=k1; K[2]=ks2; K[3]=ks2+1u; K[4]=k0+2u; K[5]=k1+3u; K[6]=ks2+4u; K[7]=k0+5u;
    }
    {
        uint32_t k0 = kb0, k1 = kb1, ks2 = k0 ^ k1 ^ 0x1BD11BDAu;
        uint32_t* K = prm.k + 8;
        K[0]=k0; K[1]=k1; K[2]=ks2; K[3]=ks2+1u; K[4]=k0+2u; K[5]=k1+3u; K[6]=ks2+4u; K[7]=k0+5u;
    }

    const int threads = 256;
    const int blocks  = (1 << 22) / threads;     // 16384
    RandomSaltPepper_9380208574641_kernel<<<blocks, threads>>>(
        in, out, prm, 1u, 2u, 0x3F800000u);
}

// round 14
// speedup vs baseline: 1.6181x; 1.0547x over previous
#include <cuda_runtime.h>
#include <cstdint>

// RandomSaltPepper — bit-exact JAX threefry (partitionable path).
// R12 = R10 resubmitted (R11 was an infra failure; theory untested).
// R5 op mix (IMAD adds on fma pipe via runtime-one mad, SHF+LOP3 rotate,
// umulhi bit-extract, FFMA blend epilogue), 8 positions per thread:
// 16 sequential threefrys amortize fixed per-thread overhead (indexing, loads,
// stores, epilogue) over twice the work (~3% fewer issue slots) and raise
// front-batched load MLP to 6.

struct TFParams {
    // keys: [0]=k0 [1]=k1 [2]=ks2 [3]=ks2+1 [4]=k0+2 [5]=k1+3 [6]=ks2+4 [7]=k0+5 (mask)
    //       [8..15] same layout (color)
    uint32_t k[16];
};

// add forced onto the fma pipe: r = a*one + b (one == 1 at runtime)
__device__ __forceinline__ uint32_t madd(uint32_t a, uint32_t one, uint32_t b) {
    uint32_t r;
    asm("mad.lo.u32 %0, %1, %2, %3;" : "=r"(r) : "r"(a), "r"(one), "r"(b));
    return r;
}

__device__ __forceinline__ void tf_round(uint32_t& x0, uint32_t& x1, int r, uint32_t one) {
    x0 = madd(x1, one, x0);                       // IMAD  (fma pipe)
    x1 = __funnelshift_l(x1, x1, r) ^ x0;         // SHF + LOP3 (alu pipe)
}

// threefry2x32, counter = (0, ctr), returns o0 ^ o1
__device__ __forceinline__ uint32_t tf_xor(const uint32_t* __restrict__ K,
                                           uint32_t ctr, uint32_t one) {
    uint32_t x0 = K[0];
    uint32_t x1 = madd(ctr, one, K[1]);
    tf_round(x0,x1,13,one); tf_round(x0,x1,15,one); tf_round(x0,x1,26,one); tf_round(x0,x1, 6,one);
    x0 = madd(K[1], one, x0);  x1 = madd(K[3], one, x1);   // += k1, += ks2+1
    tf_round(x0,x1,17,one); tf_round(x0,x1,29,one); tf_round(x0,x1,16,one); tf_round(x0,x1,24,one);
    x0 = madd(K[2], one, x0);  x1 = madd(K[4], one, x1);   // += ks2, += k0+2
    tf_round(x0,x1,13,one); tf_round(x0,x1,15,one); tf_round(x0,x1,26,one); tf_round(x0,x1, 6,one);
    x0 = madd(K[0], one, x0);  x1 = madd(K[5], one, x1);   // += k0,  += k1+3
    tf_round(x0,x1,17,one); tf_round(x0,x1,29,one); tf_round(x0,x1,16,one); tf_round(x0,x1,24,one);
    x0 = madd(K[1], one, x0);  x1 = madd(K[6], one, x1);   // += k1,  += ks2+4
    tf_round(x0,x1,13,one); tf_round(x0,x1,15,one); tf_round(x0,x1,26,one); tf_round(x0,x1, 6,one);
    x0 = madd(K[2], one, x0);  x1 = madd(K[7], one, x1);   // += ks2, += k0+5
    return x0 ^ x1;
}

// ---------------- host threefry2x32 (key derivation) ----------------
static void tf_round_h(uint32_t& x0, uint32_t& x1, int r) {
    x0 += x1;
    x1 = (x1 << r) | (x1 >> (32 - r));
    x1 ^= x0;
}
static void tf_host(uint32_t k0, uint32_t k1, uint32_t x0in, uint32_t x1in,
                    uint32_t& o0, uint32_t& o1) {
    uint32_t ks2 = k0 ^ k1 ^ 0x1BD11BDAu;
    uint32_t x0 = x0in + k0;
    uint32_t x1 = x1in + k1;
    tf_round_h(x0,x1,13); tf_round_h(x0,x1,15); tf_round_h(x0,x1,26); tf_round_h(x0,x1, 6);
    x0 += k1;  x1 += ks2 + 1u;
    tf_round_h(x0,x1,17); tf_round_h(x0,x1,29); tf_round_h(x0,x1,16); tf_round_h(x0,x1,24);
    x0 += ks2; x1 += k0 + 2u;
    tf_round_h(x0,x1,13); tf_round_h(x0,x1,15); tf_round_h(x0,x1,26); tf_round_h(x0,x1, 6);
    x0 += k0;  x1 += k1 + 3u;
    tf_round_h(x0,x1,17); tf_round_h(x0,x1,29); tf_round_h(x0,x1,16); tf_round_h(x0,x1,24);
    x0 += k1;  x1 += ks2 + 4u;
    tf_round_h(x0,x1,13); tf_round_h(x0,x1,15); tf_round_h(x0,x1,26); tf_round_h(x0,x1, 6);
    x0 += ks2; x1 += k0 + 5u;
    o0 = x0; o1 = x1;
}

// ---------------- kernel ----------------
// B=64, C=3, H=W=512. HW = 2^18, positions P = 2^24.
// 8 consecutive positions per thread -> 2 float4 per channel, 6 loads/stores.
__global__ __launch_bounds__(256, 1)
void RandomSaltPepper_9380208574641_kernel(
    const float4* __restrict__ in, float4* __restrict__ out,
    TFParams prm, uint32_t one, uint32_t two, uint32_t fone)
{
    const uint32_t* __restrict__ MK = prm.k;       // mask key block
    const uint32_t* __restrict__ CK = prm.k + 8;   // color key block

    uint32_t t  = blockIdx.x * blockDim.x + threadIdx.x;   // 0 .. 2^21-1
    uint32_t p0 = t << 3;                                  // base (b,h,w) index (mult of 8)
    uint32_t b  = p0 >> 18;                                // batch
    uint32_t q4 = (p0 & 0x3FFFFu) >> 2;                    // even float4 index within HW

    // plane base indices (float4 units: HW/4 = 2^16 per plane)
    uint32_t i0 = ((b * 3u) << 16) + q4;                   // ch0, first float4
    uint32_t i1 = i0 + (1u << 16);                         // ch1
    uint32_t i2 = i0 + (2u << 16);                         // ch2

    // 6 front-batched loads (MLP=6)
    float4 v0a = in[i0];     float4 v0b = in[i0 + 1];
    float4 v1a = in[i1];     float4 v1b = in[i1 + 1];
    float4 v2a = in[i2];     float4 v2b = in[i2 + 1];

    // z[i] = 1.0f if keep image, s[i] = 1.0f if masked & salt;  out = v*z + s
    float z[8], s[8];
#pragma unroll
    for (int i = 0; i < 8; i++) {
        uint32_t bu = tf_xor(MK, p0 + i, one);
        uint32_t bc = tf_xor(CK, p0 + i, one);
        uint32_t tb = __umulhi(bu, two);               // bit31(bu): 1 = keep image (fma)
        uint32_t sb = (~tb) & (~bc) & 1u;              // masked & salt (one LOP3)
        z[i] = __uint_as_float(tb * fone);             // IMAD (fma): 0x3F800000 or 0
        s[i] = __uint_as_float(sb * fone);             // IMAD (fma)
    }

    float4 oa, ob;
    // channel 0
    oa.x = fmaf(v0a.x, z[0], s[0]);  oa.y = fmaf(v0a.y, z[1], s[1]);
    oa.z = fmaf(v0a.z, z[2], s[2]);  oa.w = fmaf(v0a.w, z[3], s[3]);
    ob.x = fmaf(v0b.x, z[4], s[4]);  ob.y = fmaf(v0b.y, z[5], s[5]);
    ob.z = fmaf(v0b.z, z[6], s[6]);  ob.w = fmaf(v0b.w, z[7], s[7]);
    out[i0] = oa;  out[i0 + 1] = ob;
    // channel 1
    oa.x = fmaf(v1a.x, z[0], s[0]);  oa.y = fmaf(v1a.y, z[1], s[1]);
    oa.z = fmaf(v1a.z, z[2], s[2]);  oa.w = fmaf(v1a.w, z[3], s[3]);
    ob.x = fmaf(v1b.x, z[4], s[4]);  ob.y = fmaf(v1b.y, z[5], s[5]);
    ob.z = fmaf(v1b.z, z[6], s[6]);  ob.w = fmaf(v1b.w, z[7], s[7]);
    out[i1] = oa;  out[i1 + 1] = ob;
    // channel 2
    oa.x = fmaf(v2a.x, z[0], s[0]);  oa.y = fmaf(v2a.y, z[1], s[1]);
    oa.z = fmaf(v2a.z, z[2], s[2]);  oa.w = fmaf(v2a.w, z[3], s[3]);
    ob.x = fmaf(v2b.x, z[4], s[4]);  ob.y = fmaf(v2b.y, z[5], s[5]);
    ob.z = fmaf(v2b.z, z[6], s[6]);  ob.w = fmaf(v2b.w, z[7], s[7]);
    out[i2] = oa;  out[i2 + 1] = ob;
}

extern "C" void kernel_launch(void* const* d_in, const int* in_sizes, int n_in,
                              void* d_out, int out_size)
{
    const float4* in  = (const float4*)d_in[0];
    float4*       out = (float4*)d_out;

    // ---- derive JAX keys on host ----
    uint32_t k1a, k1b, k2a, k2b;
    tf_host(0u, 42u, 0u, 0u, k1a, k1b);          // k1 = split(root)[0]
    tf_host(0u, 42u, 0u, 1u, k2a, k2b);          // k2 = split(root)[1]
    uint32_t kb0, kb1;
    tf_host(k2a, k2b, 0u, 1u, kb0, kb1);         // randint internal split, child 1

    TFParams prm;
    {
        uint32_t k0 = k1a, k1 = k1b, ks2 = k0 ^ k1 ^ 0x1BD11BDAu;
        uint32_t* K = prm.k;
        K[0]=k0; K[1]=k1; K[2]=ks2; K[3]=ks2+1u; K[4]=k0+2u; K[5]=k1+3u; K[6]=ks2+4u; K[7]=k0+5u;
    }
    {
        uint32_t k0 = kb0, k1 = kb1, ks2 = k0 ^ k1 ^ 0x1BD11BDAu;
        uint32_t* K = prm.k + 8;
        K[0]=k0; K[1]=k1; K[2]=ks2; K[3]=ks2+1u; K[4]=k0+2u; K[5]=k1+3u; K[6]=ks2+4u; K[7]=k0+5u;
    }

    // P = 2^24 positions, 8 per thread -> 2^21 threads
    const int threads = 256;
    const int blocks  = (1 << 21) / threads;     // 8192
    RandomSaltPepper_9380208574641_kernel<<<blocks, threads>>>(
        in, out, prm, 1u, 2u, 0x3F800000u);
}

// round 17
// speedup vs baseline: 1.6413x; 1.0144x over previous
#include <cuda_runtime.h>
#include <cstdint>

// RandomSaltPepper — bit-exact JAX threefry (partitionable path).
// R13 = R5 core (best, 82.7us) with 128-thread blocks: identical per-thread
// code; finer wave granularity + halved per-block LDG front-batch to shave the
// wave-transition / L1tex queue-contention stall term. All op-count and
// schedule-shape variants have been explored and lose; R5 mix is the optimum:
//   round = IMAD(add, fma pipe via runtime-one mad) + SHF + LOP3 (alu pipe),
//   umulhi bit-extract (fma), FFMA blend epilogue (no SELs).

struct TFParams {
    // keys: [0]=k0 [1]=k1 [2]=ks2 [3]=ks2+1 [4]=k0+2 [5]=k1+3 [6]=ks2+4 [7]=k0+5 (mask)
    //       [8..15] same layout (color)
    uint32_t k[16];
};

// add forced onto the fma pipe: r = a*one + b (one == 1 at runtime)
__device__ __forceinline__ uint32_t madd(uint32_t a, uint32_t one, uint32_t b) {
    uint32_t r;
    asm("mad.lo.u32 %0, %1, %2, %3;" : "=r"(r) : "r"(a), "r"(one), "r"(b));
    return r;
}

__device__ __forceinline__ void tf_round(uint32_t& x0, uint32_t& x1, int r, uint32_t one) {
    x0 = madd(x1, one, x0);                       // IMAD  (fma pipe)
    x1 = __funnelshift_l(x1, x1, r) ^ x0;         // SHF + LOP3 (alu pipe)
}

// threefry2x32, counter = (0, ctr), returns o0 ^ o1
__device__ __forceinline__ uint32_t tf_xor(const uint32_t* __restrict__ K,
                                           uint32_t ctr, uint32_t one) {
    uint32_t x0 = K[0];
    uint32_t x1 = madd(ctr, one, K[1]);
    tf_round(x0,x1,13,one); tf_round(x0,x1,15,one); tf_round(x0,x1,26,one); tf_round(x0,x1, 6,one);
    x0 = madd(K[1], one, x0);  x1 = madd(K[3], one, x1);   // += k1, += ks2+1
    tf_round(x0,x1,17,one); tf_round(x0,x1,29,one); tf_round(x0,x1,16,one); tf_round(x0,x1,24,one);
    x0 = madd(K[2], one, x0);  x1 = madd(K[4], one, x1);   // += ks2, += k0+2
    tf_round(x0,x1,13,one); tf_round(x0,x1,15,one); tf_round(x0,x1,26,one); tf_round(x0,x1, 6,one);
    x0 = madd(K[0], one, x0);  x1 = madd(K[5], one, x1);   // += k0,  += k1+3
    tf_round(x0,x1,17,one); tf_round(x0,x1,29,one); tf_round(x0,x1,16,one); tf_round(x0,x1,24,one);
    x0 = madd(K[1], one, x0);  x1 = madd(K[6], one, x1);   // += k1,  += ks2+4
    tf_round(x0,x1,13,one); tf_round(x0,x1,15,one); tf_round(x0,x1,26,one); tf_round(x0,x1, 6,one);
    x0 = madd(K[2], one, x0);  x1 = madd(K[7], one, x1);   // += ks2, += k0+5
    return x0 ^ x1;
}

// ---------------- host threefry2x32 (key derivation) ----------------
static void tf_round_h(uint32_t& x0, uint32_t& x1, int r) {
    x0 += x1;
    x1 = (x1 << r) | (x1 >> (32 - r));
    x1 ^= x0;
}
static void tf_host(uint32_t k0, uint32_t k1, uint32_t x0in, uint32_t x1in,
                    uint32_t& o0, uint32_t& o1) {
    uint32_t ks2 = k0 ^ k1 ^ 0x1BD11BDAu;
    uint32_t x0 = x0in + k0;
    uint32_t x1 = x1in + k1;
    tf_round_h(x0,x1,13); tf_round_h(x0,x1,15); tf_round_h(x0,x1,26); tf_round_h(x0,x1, 6);
    x0 += k1;  x1 += ks2 + 1u;
    tf_round_h(x0,x1,17); tf_round_h(x0,x1,29); tf_round_h(x0,x1,16); tf_round_h(x0,x1,24);
    x0 += ks2; x1 += k0 + 2u;
    tf_round_h(x0,x1,13); tf_round_h(x0,x1,15); tf_round_h(x0,x1,26); tf_round_h(x0,x1, 6);
    x0 += k0;  x1 += k1 + 3u;
    tf_round_h(x0,x1,17); tf_round_h(x0,x1,29); tf_round_h(x0,x1,16); tf_round_h(x0,x1,24);
    x0 += k1;  x1 += ks2 + 4u;
    tf_round_h(x0,x1,13); tf_round_h(x0,x1,15); tf_round_h(x0,x1,26); tf_round_h(x0,x1, 6);
    x0 += ks2; x1 += k0 + 5u;
    o0 = x0; o1 = x1;
}

// ---------------- kernel ----------------
// B=64, C=3, H=W=512. HW = 2^18, positions P = 2^24. 4 consecutive positions/thread.
__global__ __launch_bounds__(128, 1)
void RandomSaltPepper_9380208574641_kernel(
    const float4* __restrict__ in, float4* __restrict__ out,
    TFParams prm, uint32_t one, uint32_t two, uint32_t fone)
{
    const uint32_t* __restrict__ MK = prm.k;       // mask key block
    const uint32_t* __restrict__ CK = prm.k + 8;   // color key block

    uint32_t t  = blockIdx.x * blockDim.x + threadIdx.x;   // 0 .. 2^22-1
    uint32_t p0 = t << 2;                                  // base (b,h,w) index
    uint32_t b  = p0 >> 18;                                // batch
    uint32_t q4 = (p0 & 0x3FFFFu) >> 2;                    // float4 index within HW

    // hoist loads — latency hides under ~570 ALU/FMA instructions below
    uint32_t i0 = ((b * 3u) << 16) + q4;
    uint32_t i1 = i0 + (1u << 16);
    uint32_t i2 = i0 + (2u << 16);
    float4 v0 = in[i0];
    float4 v1 = in[i1];
    float4 v2 = in[i2];

    // z[i] = 1.0f if position keeps the image (mask false), else 0.0f
    // s[i] = 1.0f if masked AND salt, else 0.0f            out = v*z + s
    float z[4], s[4];
#pragma unroll
    for (int i = 0; i < 4; i++) {
        uint32_t bu = tf_xor(MK, p0 + i, one);
        uint32_t bc = tf_xor(CK, p0 + i, one);
        uint32_t tb = __umulhi(bu, two);               // bit31(bu): 1 = keep image (fma)
        uint32_t sb = (~tb) & (~bc) & 1u;              // masked & salt (one LOP3)
        z[i] = __uint_as_float(tb * fone);             // IMAD (fma): 0x3F800000 or 0
        s[i] = __uint_as_float(sb * fone);             // IMAD (fma)
    }

    float4 o0, o1, o2;
    o0.x = fmaf(v0.x, z[0], s[0]);  o0.y = fmaf(v0.y, z[1], s[1]);
    o0.z = fmaf(v0.z, z[2], s[2]);  o0.w = fmaf(v0.w, z[3], s[3]);
    o1.x = fmaf(v1.x, z[0], s[0]);  o1.y = fmaf(v1.y, z[1], s[1]);
    o1.z = fmaf(v1.z, z[2], s[2]);  o1.w = fmaf(v1.w, z[3], s[3]);
    o2.x = fmaf(v2.x, z[0], s[0]);  o2.y = fmaf(v2.y, z[1], s[1]);
    o2.z = fmaf(v2.z, z[2], s[2]);  o2.w = fmaf(v2.w, z[3], s[3]);
    out[i0] = o0;
    out[i1] = o1;
    out[i2] = o2;
}

extern "C" void kernel_launch(void* const* d_in, const int* in_sizes, int n_in,
                              void* d_out, int out_size)
{
    const float4* in  = (const float4*)d_in[0];
    float4*       out = (float4*)d_out;

    // ---- derive JAX keys on host ----
    uint32_t k1a, k1b, k2a, k2b;
    tf_host(0u, 42u, 0u, 0u, k1a, k1b);          // k1 = split(root)[0]
    tf_host(0u, 42u, 0u, 1u, k2a, k2b);          // k2 = split(root)[1]
    uint32_t kb0, kb1;
    tf_host(k2a, k2b, 0u, 1u, kb0, kb1);         // randint internal split, child 1

    TFParams prm;
    {
        uint32_t k0 = k1a, k1 = k1b, ks2 = k0 ^ k1 ^ 0x1BD11BDAu;
        uint32_t* K = prm.k;
        K[0]=k0; K[1]=k1; K[2]=ks2; K[3]=ks2+1u; K[4]=k0+2u; K[5]=k1+3u; K[6]=ks2+4u; K[7]=k0+5u;
    }
    {
        uint32_t k0 = kb0, k1 = kb1, ks2 = k0 ^ k1 ^ 0x1BD11BDAu;
        uint32_t* K = prm.k + 8;
        K[0]=k0; K[1]=k1; K[2]=ks2; K[3]=ks2+1u; K[4]=k0+2u; K[5]=k1+3u; K[6]=ks2+4u; K[7]=k0+5u;
    }

    // P = 2^24 positions, 4 per thread -> 2^22 threads, 128/block
    const int threads = 128;
    const int blocks  = (1 << 22) / threads;     // 32768
    RandomSaltPepper_9380208574641_kernel<<<blocks, threads>>>(
        in, out, prm, 1u, 2u, 0x3F800000u);
}